// round 3
// baseline (speedup 1.0000x reference)
#include <cuda_runtime.h>
#include <math.h>

#define NUM_USERS 8192
#define ROW 1000
#define TOP_K 10
#define THREADS 128
#define ACTIVE 125   // 125 threads x 8 elements = 1000 = ROW

__global__ __launch_bounds__(THREADS)
void metric_kernel(const float4* __restrict__ lg4,   // 2 logit-pairs per float4
                   const int4*   __restrict__ dup4,  // 4 dup flags per int4
                   float* __restrict__ out) {
    const int user = blockIdx.x;
    const int t = threadIdx.x;

    const long f4base = (long)user * (ROW / 2);   // 500 float4 per user
    const long i4base = (long)user * (ROW / 4);   // 250 int4  per user

    const float BIG_NEG = -3.402823466e38f;  // finfo(float32).min

    __shared__ float s_l0;
    __shared__ int sc[THREADS / 32];
    __shared__ int sd[THREADS / 32];

    float4 a0, a1, a2, a3;
    int4   d0, d1;

    if (t < ACTIVE) {
        // 6 independent 16B loads, front-batched -> MLP 6
        a0 = __ldcs(&lg4[f4base + 4 * t + 0]);
        a1 = __ldcs(&lg4[f4base + 4 * t + 1]);
        a2 = __ldcs(&lg4[f4base + 4 * t + 2]);
        a3 = __ldcs(&lg4[f4base + 4 * t + 3]);
        d0 = __ldcs(&dup4[i4base + 2 * t + 0]);
        d1 = __ldcs(&dup4[i4base + 2 * t + 1]);

        // thread 0 owns element 0; publish masked l0 via smem
        if (t == 0)
            s_l0 = (d0.x != 0) ? BIG_NEG : a0.y;
    }
    __syncthreads();

    int cnt = 0, dsum = 0;

    if (t < ACTIVE) {
        const float l0 = s_l0;

        const float v0 = (d0.x != 0) ? BIG_NEG : a0.y;
        const float v1 = (d0.y != 0) ? BIG_NEG : a0.w;
        const float v2 = (d0.z != 0) ? BIG_NEG : a1.y;
        const float v3 = (d0.w != 0) ? BIG_NEG : a1.w;
        const float v4 = (d1.x != 0) ? BIG_NEG : a2.y;
        const float v5 = (d1.y != 0) ? BIG_NEG : a2.w;
        const float v6 = (d1.z != 0) ? BIG_NEG : a3.y;
        const float v7 = (d1.w != 0) ? BIG_NEG : a3.w;

        cnt = (v0 > l0) + (v1 > l0) + (v2 > l0) + (v3 > l0)
            + (v4 > l0) + (v5 > l0) + (v6 > l0) + (v7 > l0);
        dsum = d0.x + d0.y + d0.z + d0.w + d1.x + d1.y + d1.z + d1.w;
    }

    // warp reduction
    #pragma unroll
    for (int o = 16; o > 0; o >>= 1) {
        cnt  += __shfl_down_sync(0xFFFFFFFFu, cnt,  o);
        dsum += __shfl_down_sync(0xFFFFFFFFu, dsum, o);
    }

    const int wid = t >> 5;
    if ((t & 31) == 0) { sc[wid] = cnt; sd[wid] = dsum; }
    __syncthreads();

    if (t == 0) {
        int c = 0, d = 0;
        #pragma unroll
        for (int i = 0; i < THREADS / 32; i++) { c += sc[i]; d += sd[i]; }

        float pos    = (float)c;
        float intop  = (pos < (float)TOP_K) ? 1.0f : 0.0f;
        float ndcg   = intop * (0.6931471805599453f / logf(pos + 2.0f));
        float weight = (d != (ROW - 1)) ? 1.0f : 0.0f;

        out[user]                 = intop;
        out[NUM_USERS + user]     = ndcg;
        out[2 * NUM_USERS + user] = weight;
    }
}

extern "C" void kernel_launch(void* const* d_in, const int* in_sizes, int n_in,
                              void* d_out, int out_size) {
    const float4* lg4  = (const float4*)d_in[0];
    const int4*   dup4 = (const int4*)d_in[1];
    float*        out  = (float*)d_out;

    metric_kernel<<<NUM_USERS, THREADS>>>(lg4, dup4, out);
}

// round 4
// speedup vs baseline: 1.0563x; 1.0563x over previous
#include <cuda_runtime.h>
#include <math.h>

#define NUM_USERS 8192
#define ROW 1000
#define TOP_K 10
#define THREADS 256
#define ACTIVE 250          // 250 threads x 4 elements = 1000 = ROW
#define GRID 1184           // 148 SMs * 8 blocks

__global__ __launch_bounds__(THREADS)
void metric_kernel(const float4* __restrict__ lg4,   // 2 logit-pairs per float4
                   const int4*   __restrict__ dup4,  // 4 dup flags per int4
                   float* __restrict__ out) {
    const int t = threadIdx.x;
    const bool act = (t < ACTIVE);
    const float BIG_NEG = -3.402823466e38f;  // finfo(float32).min

    __shared__ int sc[THREADS / 32];
    __shared__ int sd[THREADS / 32];

    int user = blockIdx.x;

    // current-user registers
    float4 a, b; int4 dd; int d0raw = 0; float l0raw = 0.f;

    if (act) {  // user < NUM_USERS always true on first iter (GRID < NUM_USERS)
        const long f4 = (long)user * (ROW / 2);
        const long i4 = (long)user * (ROW / 4);
        a  = __ldcs(&lg4[f4 + 2 * t]);
        b  = __ldcs(&lg4[f4 + 2 * t + 1]);
        dd = __ldcs(&dup4[i4 + t]);
        d0raw = __ldg(&((const int*)dup4)[i4 * 4]);
        l0raw = __ldg(&((const float*)lg4)[f4 * 4 + 1]);
    }

    while (user < NUM_USERS) {
        const int nxt = user + GRID;

        // prefetch next user while current data is consumed
        float4 na, nb; int4 ndd; int nd0 = 0; float nl0 = 0.f;
        if (act && nxt < NUM_USERS) {
            const long f4 = (long)nxt * (ROW / 2);
            const long i4 = (long)nxt * (ROW / 4);
            na  = __ldcs(&lg4[f4 + 2 * t]);
            nb  = __ldcs(&lg4[f4 + 2 * t + 1]);
            ndd = __ldcs(&dup4[i4 + t]);
            nd0 = __ldg(&((const int*)dup4)[i4 * 4]);
            nl0 = __ldg(&((const float*)lg4)[f4 * 4 + 1]);
        }

        // ---- consume current user ----
        int cnt = 0, dsum = 0;
        if (act) {
            const float l0 = (d0raw != 0) ? BIG_NEG : l0raw;
            const float v0 = (dd.x != 0) ? BIG_NEG : a.y;
            const float v1 = (dd.y != 0) ? BIG_NEG : a.w;
            const float v2 = (dd.z != 0) ? BIG_NEG : b.y;
            const float v3 = (dd.w != 0) ? BIG_NEG : b.w;
            cnt  = (v0 > l0) + (v1 > l0) + (v2 > l0) + (v3 > l0);
            dsum = dd.x + dd.y + dd.z + dd.w;
        }

        #pragma unroll
        for (int o = 16; o > 0; o >>= 1) {
            cnt  += __shfl_down_sync(0xFFFFFFFFu, cnt,  o);
            dsum += __shfl_down_sync(0xFFFFFFFFu, dsum, o);
        }

        const int wid = t >> 5;
        if ((t & 31) == 0) { sc[wid] = cnt; sd[wid] = dsum; }
        __syncthreads();

        if (t == 0) {
            int c = 0, d = 0;
            #pragma unroll
            for (int i = 0; i < THREADS / 32; i++) { c += sc[i]; d += sd[i]; }

            float pos    = (float)c;
            float intop  = (pos < (float)TOP_K) ? 1.0f : 0.0f;
            float ndcg   = intop * (0.6931471805599453f / logf(pos + 2.0f));
            float weight = (d != (ROW - 1)) ? 1.0f : 0.0f;

            out[user]                 = intop;
            out[NUM_USERS + user]     = ndcg;
            out[2 * NUM_USERS + user] = weight;
        }
        __syncthreads();  // protect sc/sd before next iteration's writes

        // rotate pipeline
        a = na; b = nb; dd = ndd; d0raw = nd0; l0raw = nl0;
        user = nxt;
    }
}

extern "C" void kernel_launch(void* const* d_in, const int* in_sizes, int n_in,
                              void* d_out, int out_size) {
    const float4* lg4  = (const float4*)d_in[0];
    const int4*   dup4 = (const int4*)d_in[1];
    float*        out  = (float*)d_out;

    metric_kernel<<<GRID, THREADS>>>(lg4, dup4, out);
}

// round 5
// speedup vs baseline: 1.4592x; 1.3814x over previous
#include <cuda_runtime.h>
#include <math.h>

#define NUM_USERS 8192
#define ROW 1000
#define TOP_K 10
#define THREADS 256
#define WPB (THREADS / 32)   // warps (users) per block

__global__ __launch_bounds__(THREADS)
void metric_kernel(const float4* __restrict__ lg4,   // 2 logit-pairs per float4
                   const int4*   __restrict__ dup4,  // 4 dup flags per int4
                   float* __restrict__ out) {
    const int lane = threadIdx.x & 31;
    const int user = blockIdx.x * WPB + (threadIdx.x >> 5);

    const float BIG_NEG = -3.402823466e38f;  // finfo(float32).min

    const long F = (long)user * (ROW / 2);   // 500 float4 per user
    const long D = (long)user * (ROW / 4);   // 250 int4  per user

    // 8 units per lane, unit u_k = lane + 32k; unit u = elements [4u, 4u+4)
    // two-deep register pipeline: current (d,a,b), next (nd,na,nb)
    int4 d, nd; float4 a, b, na, nb;

    d  = __ldcs(&dup4[D + lane]);
    a  = __ldcs(&lg4[F + 2 * lane]);
    b  = __ldcs(&lg4[F + 2 * lane + 1]);
    nd = __ldcs(&dup4[D + lane + 32]);
    na = __ldcs(&lg4[F + 2 * (lane + 32)]);
    nb = __ldcs(&lg4[F + 2 * (lane + 32) + 1]);

    // element 0 lives in lane 0's unit 0: dup = d.x, logit = a.y
    const float l0c = (d.x != 0) ? BIG_NEG : a.y;
    const float l0  = __shfl_sync(0xFFFFFFFFu, l0c, 0);

    int cnt = 0, dsum = 0;

    #pragma unroll
    for (int k = 0; k < 8; k++) {
        // prefetch unit k+2 while consuming unit k
        int4 pd; float4 pa, pb;
        if (k < 6) {
            const int u = lane + 32 * (k + 2);
            if (u < (ROW / 4)) {
                pd = __ldcs(&dup4[D + u]);
                pa = __ldcs(&lg4[F + 2 * u]);
                pb = __ldcs(&lg4[F + 2 * u + 1]);
            } else {
                // neutral: dup=0 (dsum+=0), logits=BIG_NEG (never > l0)
                pd = make_int4(0, 0, 0, 0);
                pa = make_float4(0.f, BIG_NEG, 0.f, BIG_NEG);
                pb = pa;
            }
        }

        const float v0 = (d.x != 0) ? BIG_NEG : a.y;
        const float v1 = (d.y != 0) ? BIG_NEG : a.w;
        const float v2 = (d.z != 0) ? BIG_NEG : b.y;
        const float v3 = (d.w != 0) ? BIG_NEG : b.w;
        cnt  += (v0 > l0) + (v1 > l0) + (v2 > l0) + (v3 > l0);
        dsum += d.x + d.y + d.z + d.w;

        d = nd; a = na; b = nb;
        if (k < 6) { nd = pd; na = pa; nb = pb; }
    }

    // warp-only reduction — no smem, no barriers
    #pragma unroll
    for (int o = 16; o > 0; o >>= 1) {
        cnt  += __shfl_down_sync(0xFFFFFFFFu, cnt,  o);
        dsum += __shfl_down_sync(0xFFFFFFFFu, dsum, o);
    }

    if (lane == 0) {
        float pos    = (float)cnt;
        float intop  = (pos < (float)TOP_K) ? 1.0f : 0.0f;
        float ndcg   = intop * (0.6931471805599453f / logf(pos + 2.0f));
        float weight = (dsum != (ROW - 1)) ? 1.0f : 0.0f;

        out[user]                 = intop;
        out[NUM_USERS + user]     = ndcg;
        out[2 * NUM_USERS + user] = weight;
    }
}

extern "C" void kernel_launch(void* const* d_in, const int* in_sizes, int n_in,
                              void* d_out, int out_size) {
    const float4* lg4  = (const float4*)d_in[0];
    const int4*   dup4 = (const int4*)d_in[1];
    float*        out  = (float*)d_out;

    metric_kernel<<<NUM_USERS / WPB, THREADS>>>(lg4, dup4, out);
}